// round 4
// baseline (speedup 1.0000x reference)
#include <cuda_runtime.h>

#define BB 4
#define TT 2048
#define HH 16
#define DD 64
#define CC 1024
#define MM (BB * TT)   // 8192

// Scratch (device globals: no allocation allowed in kernel_launch)
__device__ float g_q[(long long)BB * HH * TT * DD];   // [B,H,T,D]
__device__ float g_k[(long long)BB * HH * TT * DD];
__device__ float g_v[(long long)BB * HH * TT * DD];
__device__ float g_y[(long long)MM * CC];             // [B,T,C] attention output

// ---------------------------------------------------------------------------
// SGEMM: out = A[M,K] @ W[K,N] + bias[N]
// BM=BN=128, BK=16, 256 threads, 8x8 per-thread microtile.
// Two-stage smem double buffering; one __syncthreads per k-tile.
// MODE 0: out row-major [M,N]
// MODE 1: out scattered to [B,H,T,D]  (m = b*T + t, n = h*D + d)
// ---------------------------------------------------------------------------
template <int MODE>
__global__ void __launch_bounds__(256)
gemm128(const float* __restrict__ A, const float* __restrict__ W,
        const float* __restrict__ bias, float* __restrict__ out,
        int M, int N, int K)
{
    __shared__ float As[2][16][128];   // transposed A tile: As[s][k][m]
    __shared__ float Bs[2][16][128];   // Bs[s][k][n]

    const int tid = threadIdx.x;
    const int bm = blockIdx.y * 128;
    const int bn = blockIdx.x * 128;
    const int ty = tid >> 4;          // 0..15
    const int tx = tid & 15;          // 0..15

    const int ar = tid >> 2;          // 0..63  (rows ar and ar+64)
    const int ac = (tid & 3) << 2;    // 0,4,8,12
    const int br = tid >> 4;          // 0..15
    const int bc = (tid & 15) << 3;   // 0..120

    float acc[8][8];
#pragma unroll
    for (int i = 0; i < 8; i++)
#pragma unroll
        for (int j = 0; j < 8; j++) acc[i][j] = 0.f;

    const float* Aptr0 = A + (long long)(bm + ar) * K + ac;
    const float* Aptr1 = A + (long long)(bm + ar + 64) * K + ac;
    const float* Wptr  = W + (long long)br * N + bn + bc;

    {
        float4 a0 = *(const float4*)(Aptr0);
        float4 a1 = *(const float4*)(Aptr1);
        float4 b0 = *(const float4*)(Wptr);
        float4 b1 = *(const float4*)(Wptr + 4);
        As[0][ac + 0][ar] = a0.x;
        As[0][ac + 1][ar] = a0.y;
        As[0][ac + 2][ar] = a0.z;
        As[0][ac + 3][ar] = a0.w;
        As[0][ac + 0][ar + 64] = a1.x;
        As[0][ac + 1][ar + 64] = a1.y;
        As[0][ac + 2][ar + 64] = a1.z;
        As[0][ac + 3][ar + 64] = a1.w;
        *(float4*)&Bs[0][br][bc]     = b0;
        *(float4*)&Bs[0][br][bc + 4] = b1;
    }
    __syncthreads();

    int buf = 0;
    for (int k0 = 0; k0 < K; k0 += 16) {
        const int next = buf ^ 1;
        const bool has_next = (k0 + 16) < K;

        float4 a0, a1, b0, b1;
        if (has_next) {
            a0 = *(const float4*)(Aptr0 + k0 + 16);
            a1 = *(const float4*)(Aptr1 + k0 + 16);
            b0 = *(const float4*)(Wptr + (long long)(k0 + 16) * N);
            b1 = *(const float4*)(Wptr + (long long)(k0 + 16) * N + 4);
        }

#pragma unroll
        for (int kk = 0; kk < 16; kk++) {
            float af[8], bf[8];
            *(float4*)&af[0] = *(const float4*)&As[buf][kk][ty * 8];
            *(float4*)&af[4] = *(const float4*)&As[buf][kk][ty * 8 + 4];
            *(float4*)&bf[0] = *(const float4*)&Bs[buf][kk][tx * 8];
            *(float4*)&bf[4] = *(const float4*)&Bs[buf][kk][tx * 8 + 4];
#pragma unroll
            for (int i = 0; i < 8; i++)
#pragma unroll
                for (int j = 0; j < 8; j++)
                    acc[i][j] += af[i] * bf[j];
        }

        if (has_next) {
            As[next][ac + 0][ar] = a0.x;
            As[next][ac + 1][ar] = a0.y;
            As[next][ac + 2][ar] = a0.z;
            As[next][ac + 3][ar] = a0.w;
            As[next][ac + 0][ar + 64] = a1.x;
            As[next][ac + 1][ar + 64] = a1.y;
            As[next][ac + 2][ar + 64] = a1.z;
            As[next][ac + 3][ar + 64] = a1.w;
            *(float4*)&Bs[next][br][bc]     = b0;
            *(float4*)&Bs[next][br][bc + 4] = b1;
            __syncthreads();
        }
        buf = next;
    }

    float bv[8];
#pragma unroll
    for (int j = 0; j < 8; j++) bv[j] = bias[bn + tx * 8 + j];

#pragma unroll
    for (int i = 0; i < 8; i++) {
        int m = bm + ty * 8 + i;
#pragma unroll
        for (int j = 0; j < 8; j++) {
            int n = bn + tx * 8 + j;
            float c = acc[i][j] + bv[j];
            if (MODE == 0) {
                out[(long long)m * N + n] = c;
            } else {
                int b = m >> 11;            // T = 2048
                int t = m & (TT - 1);
                int h = n >> 6;             // D = 64
                int d = n & (DD - 1);
                out[(((long long)(b * HH + h)) * TT + t) * DD + d] = c;
            }
        }
    }
}

// ---------------------------------------------------------------------------
// Flash-attention (fp32), causal. One block = 64 query rows of one (b,h).
// 128 threads: thread (ty 0..15, tx 0..7) owns S/O rows 4ty..4ty+3,
// cols 8tx..8tx+7. Online softmax across key tiles of 64.
// K stored TRANSPOSED in smem (Kts[d][row], pad 68) so the S-loop reads K
// with conflict-free LDS.128; Ps aliases Kts after the S pass.
// smem floats: Qs 64*65 + Kts 64*68 + Vs 64*64 = 12608 -> 50432 B.
// ---------------------------------------------------------------------------
#define ATT_SMEM_FLOATS (64 * 65 + 64 * 68 + 64 * 64)

__global__ void __launch_bounds__(128)
attn64(const float* __restrict__ gq, const float* __restrict__ gk,
       const float* __restrict__ gv, float* __restrict__ gy)
{
    extern __shared__ float sm[];
    float* Qs  = sm;                  // [64][65] row-major
    float* Kts = Qs + 64 * 65;        // [64][68] K transposed: Kts[d][row]
    float* Vs  = Kts + 64 * 68;       // [64][64] row-major
    float* Ps  = Kts;                 // alias: [64 rows][68] after S pass

    // LPT: longest causal chains (largest qi) launch first.
    const int qi = (int)gridDim.x - 1 - (int)blockIdx.x;   // 0..31
    const int bh = blockIdx.y;                              // 0..63
    const float* Qg = gq + ((long long)bh * TT + qi * 64) * DD;
    const float* Kg = gk + (long long)bh * TT * DD;
    const float* Vg = gv + (long long)bh * TT * DD;

    const int tid = threadIdx.x;
    const int ty = tid >> 3;   // 0..15
    const int tx = tid & 7;    // 0..7

    // Load Q tile with 1/sqrt(D) folded in.
    for (int e = tid; e < 64 * 16; e += 128) {
        int r  = e >> 4;
        int d4 = (e & 15) << 2;
        float4 v = *(const float4*)(Qg + r * DD + d4);
        Qs[r * 65 + d4 + 0] = v.x * 0.125f;
        Qs[r * 65 + d4 + 1] = v.y * 0.125f;
        Qs[r * 65 + d4 + 2] = v.z * 0.125f;
        Qs[r * 65 + d4 + 3] = v.w * 0.125f;
    }

    float m_i[4], l_i[4], oacc[4][8];
#pragma unroll
    for (int i = 0; i < 4; i++) {
        m_i[i] = -1e30f;
        l_i[i] = 0.f;
#pragma unroll
        for (int j = 0; j < 8; j++) oacc[i][j] = 0.f;
    }

    for (int kj = 0; kj <= qi; kj++) {
        __syncthreads();   // previous iter's reads of Kts/Ps/Vs complete
        const float* Kt = Kg + (long long)kj * 64 * DD;
        const float* Vt = Vg + (long long)kj * 64 * DD;
        for (int e = tid; e < 64 * 16; e += 128) {
            int r  = e >> 4;
            int d4 = (e & 15) << 2;
            float4 kv = *(const float4*)(Kt + r * DD + d4);
            Kts[(d4 + 0) * 68 + r] = kv.x;
            Kts[(d4 + 1) * 68 + r] = kv.y;
            Kts[(d4 + 2) * 68 + r] = kv.z;
            Kts[(d4 + 3) * 68 + r] = kv.w;
            *(float4*)(Vs + r * 64 + d4) = *(const float4*)(Vt + r * DD + d4);
        }
        __syncthreads();

        // S = Q @ K^T (scale folded into Q). K read via conflict-free LDS.128.
        float s[4][8];
#pragma unroll
        for (int i = 0; i < 4; i++)
#pragma unroll
            for (int j = 0; j < 8; j++) s[i][j] = 0.f;

#pragma unroll 4
        for (int d = 0; d < 64; d++) {
            float qf[4], kf[8];
            *(float4*)&kf[0] = *(const float4*)&Kts[d * 68 + tx * 8];
            *(float4*)&kf[4] = *(const float4*)&Kts[d * 68 + tx * 8 + 4];
#pragma unroll
            for (int i = 0; i < 4; i++) qf[i] = Qs[(ty * 4 + i) * 65 + d];
#pragma unroll
            for (int i = 0; i < 4; i++)
#pragma unroll
                for (int j = 0; j < 8; j++)
                    s[i][j] += qf[i] * kf[j];
        }

        // Causal mask on the diagonal tile
        if (kj == qi) {
#pragma unroll
            for (int i = 0; i < 4; i++)
#pragma unroll
                for (int j = 0; j < 8; j++)
                    if (tx * 8 + j > ty * 4 + i) s[i][j] = -1e30f;
        }

        // Online softmax update (row stats shared by the 8 tx-lanes of a row)
#pragma unroll
        for (int i = 0; i < 4; i++) {
            float rmax = s[i][0];
#pragma unroll
            for (int j = 1; j < 8; j++) rmax = fmaxf(rmax, s[i][j]);
#pragma unroll
            for (int o = 1; o < 8; o <<= 1)
                rmax = fmaxf(rmax, __shfl_xor_sync(0xffffffffu, rmax, o));
            float mnew  = fmaxf(m_i[i], rmax);
            float alpha = __expf(m_i[i] - mnew);
            float rsum = 0.f;
#pragma unroll
            for (int j = 0; j < 8; j++) {
                float p = __expf(s[i][j] - mnew);
                s[i][j] = p;
                rsum += p;
            }
#pragma unroll
            for (int o = 1; o < 8; o <<= 1)
                rsum += __shfl_xor_sync(0xffffffffu, rsum, o);
            l_i[i] = l_i[i] * alpha + rsum;
            m_i[i] = mnew;
#pragma unroll
            for (int j = 0; j < 8; j++) oacc[i][j] *= alpha;
        }

        __syncthreads();   // all Kts reads done before overwriting as Ps
#pragma unroll
        for (int i = 0; i < 4; i++)
#pragma unroll
            for (int j = 0; j < 8; j++)
                Ps[(ty * 4 + i) * 68 + tx * 8 + j] = s[i][j];
        __syncthreads();

        // O += P @ V, chunked by 4 along s0; all smem reads are LDS.128.
#pragma unroll 2
        for (int s0 = 0; s0 < 64; s0 += 4) {
            float4 pf4[4];
#pragma unroll
            for (int i = 0; i < 4; i++)
                pf4[i] = *(const float4*)&Ps[(ty * 4 + i) * 68 + s0];
            float4 va[4], vb[4];
#pragma unroll
            for (int u = 0; u < 4; u++) {
                va[u] = *(const float4*)(Vs + (s0 + u) * 64 + tx * 8);
                vb[u] = *(const float4*)(Vs + (s0 + u) * 64 + tx * 8 + 4);
            }
#pragma unroll
            for (int u = 0; u < 4; u++) {
                float vf[8];
                *(float4*)&vf[0] = va[u];
                *(float4*)&vf[4] = vb[u];
#pragma unroll
                for (int i = 0; i < 4; i++) {
                    float p = ((const float*)&pf4[i])[u];
#pragma unroll
                    for (int j = 0; j < 8; j++)
                        oacc[i][j] += p * vf[j];
                }
            }
        }
    }

    // Normalize and write y[b][t][h*D + d] with vector stores.
    const int b = bh >> 4;   // H = 16
    const int h = bh & 15;
#pragma unroll
    for (int i = 0; i < 4; i++) {
        float inv = 1.f / l_i[i];
        int t = qi * 64 + ty * 4 + i;
        float* dst = gy + ((long long)b * TT + t) * CC + h * DD + tx * 8;
        float4 o0 = make_float4(oacc[i][0] * inv, oacc[i][1] * inv,
                                oacc[i][2] * inv, oacc[i][3] * inv);
        float4 o1 = make_float4(oacc[i][4] * inv, oacc[i][5] * inv,
                                oacc[i][6] * inv, oacc[i][7] * inv);
        *(float4*)dst       = o0;
        *(float4*)(dst + 4) = o1;
    }
}

// ---------------------------------------------------------------------------
extern "C" void kernel_launch(void* const* d_in, const int* in_sizes, int n_in,
                              void* d_out, int out_size)
{
    const float* x  = (const float*)d_in[0];
    const float* Wq = (const float*)d_in[1];
    const float* bq = (const float*)d_in[2];
    const float* Wk = (const float*)d_in[3];
    const float* bk = (const float*)d_in[4];
    const float* Wv = (const float*)d_in[5];
    const float* bv = (const float*)d_in[6];
    const float* Wp = (const float*)d_in[7];
    const float* bp = (const float*)d_in[8];
    float* out = (float*)d_out;

    float *q, *k, *v, *y;
    cudaGetSymbolAddress((void**)&q, g_q);
    cudaGetSymbolAddress((void**)&k, g_k);
    cudaGetSymbolAddress((void**)&v, g_v);
    cudaGetSymbolAddress((void**)&y, g_y);

    dim3 gblk(256);
    dim3 ggrid(CC / 128, MM / 128);   // (8, 64)

    gemm128<1><<<ggrid, gblk>>>(x, Wq, bq, q, MM, CC, CC);
    gemm128<1><<<ggrid, gblk>>>(x, Wk, bk, k, MM, CC, CC);
    gemm128<1><<<ggrid, gblk>>>(x, Wv, bv, v, MM, CC, CC);

    const int att_smem = ATT_SMEM_FLOATS * (int)sizeof(float);   // 50432 B
    cudaFuncSetAttribute(attn64, cudaFuncAttributeMaxDynamicSharedMemorySize,
                         att_smem);
    attn64<<<dim3(TT / 64, BB * HH), 128, att_smem>>>(q, k, v, y);

    gemm128<0><<<ggrid, gblk>>>(y, Wp, bp, out, MM, CC, CC);
}

// round 7
// speedup vs baseline: 1.2872x; 1.2872x over previous
#include <cuda_runtime.h>
#include <mma.h>

using namespace nvcuda;

#define BB 4
#define TT 2048
#define HH 16
#define DD 64
#define CC 1024
#define MM (BB * TT)   // 8192

// Scratch (device globals: no allocation allowed in kernel_launch)
__device__ float g_q[(long long)MM * CC];   // [M, C] = [b*T+t, h*64+d]
__device__ float g_k[(long long)MM * CC];
__device__ float g_v[(long long)MM * CC];
__device__ float g_y[(long long)MM * CC];   // attention output [M, C]

// ---------------------------------------------------------------------------
// TF32 tensor-core GEMM: out = A[M,K] @ W[K,N]   (bias added by epilogue)
// BM=BN=128, BK=16, 256 threads = 8 warps; warp tile 32x64 (2x4 m16n16k8
// fragments). Double-buffered smem, one __syncthreads per k-tile.
// TF32 rounding applied once at the smem loaders.
// ---------------------------------------------------------------------------
__device__ __forceinline__ float4 to_tf32x4(float4 v) {
    v.x = wmma::__float_to_tf32(v.x);
    v.y = wmma::__float_to_tf32(v.y);
    v.z = wmma::__float_to_tf32(v.z);
    v.w = wmma::__float_to_tf32(v.w);
    return v;
}

__global__ void __launch_bounds__(256)
gemm_tc(const float* __restrict__ A, const float* __restrict__ W,
        float* __restrict__ out, int M, int N, int K)
{
    __shared__ float As[2][128][20];    // [buf][m][k], pad to 20
    __shared__ float Bs[2][16][136];    // [buf][k][n], pad to 136

    const int tid = threadIdx.x;
    const int w   = tid >> 5;           // 0..7
    const int wr  = w >> 1;             // 0..3  (m block of 32)
    const int wc  = w & 1;              // 0..1  (n block of 64)
    const int bm  = blockIdx.y * 128;
    const int bn  = blockIdx.x * 128;

    // A loader: rows tid>>2 and +64, cols (tid&3)*4
    const int am = tid >> 2;            // 0..63
    const int ak = (tid & 3) << 2;      // 0,4,8,12
    // B loader: row tid>>4 (0..15), cols (tid&15)*8 (two float4)
    const int bk = tid >> 4;            // 0..15
    const int bnn = (tid & 15) << 3;    // 0..120

    wmma::fragment<wmma::accumulator, 16, 16, 8, float> acc[2][4];
#pragma unroll
    for (int i = 0; i < 2; i++)
#pragma unroll
        for (int j = 0; j < 4; j++)
            wmma::fill_fragment(acc[i][j], 0.0f);

    const float* Aptr0 = A + (long long)(bm + am) * K + ak;
    const float* Aptr1 = A + (long long)(bm + am + 64) * K + ak;
    const float* Wptr  = W + (long long)bk * N + bn + bnn;

    // Preload tile 0 (tf32-rounded into smem).
    {
        float4 a0 = to_tf32x4(*(const float4*)(Aptr0));
        float4 a1 = to_tf32x4(*(const float4*)(Aptr1));
        float4 b0 = to_tf32x4(*(const float4*)(Wptr));
        float4 b1 = to_tf32x4(*(const float4*)(Wptr + 4));
        *(float4*)&As[0][am][ak]      = a0;
        *(float4*)&As[0][am + 64][ak] = a1;
        *(float4*)&Bs[0][bk][bnn]     = b0;
        *(float4*)&Bs[0][bk][bnn + 4] = b1;
    }
    __syncthreads();

    int buf = 0;
    for (int k0 = 0; k0 < K; k0 += 16) {
        const int next = buf ^ 1;
        const bool has_next = (k0 + 16) < K;

        float4 a0, a1, b0, b1;
        if (has_next) {
            a0 = *(const float4*)(Aptr0 + k0 + 16);
            a1 = *(const float4*)(Aptr1 + k0 + 16);
            b0 = *(const float4*)(Wptr + (long long)(k0 + 16) * N);
            b1 = *(const float4*)(Wptr + (long long)(k0 + 16) * N + 4);
        }

#pragma unroll
        for (int kk = 0; kk < 16; kk += 8) {
            wmma::fragment<wmma::matrix_a, 16, 16, 8, wmma::precision::tf32,
                           wmma::row_major> afr[2];
            wmma::fragment<wmma::matrix_b, 16, 16, 8, wmma::precision::tf32,
                           wmma::row_major> bfr[4];
#pragma unroll
            for (int im = 0; im < 2; im++)
                wmma::load_matrix_sync(afr[im],
                                       &As[buf][wr * 32 + im * 16][kk], 20);
#pragma unroll
            for (int in = 0; in < 4; in++)
                wmma::load_matrix_sync(bfr[in],
                                       &Bs[buf][kk][wc * 64 + in * 16], 136);
#pragma unroll
            for (int im = 0; im < 2; im++)
#pragma unroll
                for (int in = 0; in < 4; in++)
                    wmma::mma_sync(acc[im][in], afr[im], bfr[in], acc[im][in]);
        }

        if (has_next) {
            *(float4*)&As[next][am][ak]      = to_tf32x4(a0);
            *(float4*)&As[next][am + 64][ak] = to_tf32x4(a1);
            *(float4*)&Bs[next][bk][bnn]     = to_tf32x4(b0);
            *(float4*)&Bs[next][bk][bnn + 4] = to_tf32x4(b1);
            __syncthreads();
        }
        buf = next;
    }

    // Direct stores to global (bias added by epilogue kernel).
#pragma unroll
    for (int im = 0; im < 2; im++)
#pragma unroll
        for (int in = 0; in < 4; in++) {
            float* dst = out + (long long)(bm + wr * 32 + im * 16) * N
                             + bn + wc * 64 + in * 16;
            wmma::store_matrix_sync(dst, acc[im][in], N, wmma::mem_row_major);
        }
}

// ---------------------------------------------------------------------------
// In-place bias add over [M, C]; one float4 per thread.
// ---------------------------------------------------------------------------
__global__ void __launch_bounds__(256)
bias_add4(float* __restrict__ buf, const float* __restrict__ bias)
{
    long long i4 = ((long long)blockIdx.x * blockDim.x + threadIdx.x) << 2;
    float4 v = *(float4*)(buf + i4);
    float4 b = *(const float4*)(bias + (int)(i4 & (CC - 1)));
    v.x += b.x; v.y += b.y; v.z += b.z; v.w += b.w;
    *(float4*)(buf + i4) = v;
}

// ---------------------------------------------------------------------------
// Flash-attention (fp32), causal. One block = 64 query rows of one (b,h).
// Q/K/V read from [M, C] layout (row stride C, head offset h*64).
// 128 threads: thread (ty 0..15, tx 0..7) owns S/O rows 4ty..4ty+3,
// cols 8tx..8tx+7. Online softmax across key tiles of 64.
// All smem matrix traffic is LDS.128/STS.128.
// smem floats: Qs 64*68 + Kts 64*68 + Vs 64*64 = 12800 -> 51200 B.
// ---------------------------------------------------------------------------
#define ATT_SMEM_FLOATS (64 * 68 + 64 * 68 + 64 * 64)

__global__ void __launch_bounds__(128)
attn64(const float* __restrict__ gq, const float* __restrict__ gk,
       const float* __restrict__ gv, float* __restrict__ gy)
{
    extern __shared__ float sm[];
    float* Qs  = sm;                  // [64][68]
    float* Kts = Qs + 64 * 68;        // [64][68] K transposed: Kts[d][row]
    float* Vs  = Kts + 64 * 68;       // [64][64]
    float* Ps  = Kts;                 // alias: [64 rows][68] after S pass

    // LPT: longest causal chains (largest qi) launch first.
    const int qi = (int)gridDim.x - 1 - (int)blockIdx.x;   // 0..31
    const int bh = blockIdx.y;                              // 0..63
    const int b  = bh >> 4;   // H = 16
    const int h  = bh & 15;

    // [M, C] layout: row m = b*T + t, column h*64 + d; row stride C.
    const float* Qg = gq + ((long long)b * TT + qi * 64) * CC + h * DD;
    const float* Kg = gk + (long long)b * TT * CC + h * DD;
    const float* Vg = gv + (long long)b * TT * CC + h * DD;

    const int tid = threadIdx.x;
    const int ty = tid >> 3;   // 0..15
    const int tx = tid & 7;    // 0..7

    // Load Q tile with 1/sqrt(D) folded in (vector stores, rows 16B-aligned).
    for (int e = tid; e < 64 * 16; e += 128) {
        int r  = e >> 4;
        int d4 = (e & 15) << 2;
        float4 v = *(const float4*)(Qg + (long long)r * CC + d4);
        v.x *= 0.125f; v.y *= 0.125f; v.z *= 0.125f; v.w *= 0.125f;
        *(float4*)&Qs[r * 68 + d4] = v;
    }

    float m_i[4], l_i[4], oacc[4][8];
#pragma unroll
    for (int i = 0; i < 4; i++) {
        m_i[i] = -1e30f;
        l_i[i] = 0.f;
#pragma unroll
        for (int j = 0; j < 8; j++) oacc[i][j] = 0.f;
    }

    for (int kj = 0; kj <= qi; kj++) {
        __syncthreads();   // previous iter's reads of Kts/Ps/Vs complete
        const float* Kt = Kg + (long long)kj * 64 * CC;
        const float* Vt = Vg + (long long)kj * 64 * CC;
        for (int e = tid; e < 64 * 16; e += 128) {
            int r  = e >> 4;
            int d4 = (e & 15) << 2;
            float4 kv = *(const float4*)(Kt + (long long)r * CC + d4);
            Kts[(d4 + 0) * 68 + r] = kv.x;
            Kts[(d4 + 1) * 68 + r] = kv.y;
            Kts[(d4 + 2) * 68 + r] = kv.z;
            Kts[(d4 + 3) * 68 + r] = kv.w;
            *(float4*)(Vs + r * 64 + d4) =
                *(const float4*)(Vt + (long long)r * CC + d4);
        }
        __syncthreads();

        // S = Q @ K^T (scale folded into Q). 12 LDS.128 per 4-d chunk.
        float s[4][8];
#pragma unroll
        for (int i = 0; i < 4; i++)
#pragma unroll
            for (int j = 0; j < 8; j++) s[i][j] = 0.f;

#pragma unroll 2
        for (int d0 = 0; d0 < 64; d0 += 4) {
            float4 qv[4];
#pragma unroll
            for (int i = 0; i < 4; i++)
                qv[i] = *(const float4*)&Qs[(ty * 4 + i) * 68 + d0];
#pragma unroll
            for (int u = 0; u < 4; u++) {
                int d = d0 + u;
                float kf[8];
                *(float4*)&kf[0] = *(const float4*)&Kts[d * 68 + tx * 8];
                *(float4*)&kf[4] = *(const float4*)&Kts[d * 68 + tx * 8 + 4];
#pragma unroll
                for (int i = 0; i < 4; i++) {
                    float q = ((const float*)&qv[i])[u];
#pragma unroll
                    for (int j = 0; j < 8; j++)
                        s[i][j] += q * kf[j];
                }
            }
        }

        // Causal mask on the diagonal tile
        if (kj == qi) {
#pragma unroll
            for (int i = 0; i < 4; i++)
#pragma unroll
                for (int j = 0; j < 8; j++)
                    if (tx * 8 + j > ty * 4 + i) s[i][j] = -1e30f;
        }

        // Online softmax update (row stats shared by the 8 tx-lanes of a row)
#pragma unroll
        for (int i = 0; i < 4; i++) {
            float rmax = s[i][0];
#pragma unroll
            for (int j = 1; j < 8; j++) rmax = fmaxf(rmax, s[i][j]);
#pragma unroll
            for (int o = 1; o < 8; o <<= 1)
                rmax = fmaxf(rmax, __shfl_xor_sync(0xffffffffu, rmax, o));
            float mnew  = fmaxf(m_i[i], rmax);
            float alpha = __expf(m_i[i] - mnew);
            float rsum = 0.f;
#pragma unroll
            for (int j = 0; j < 8; j++) {
                float p = __expf(s[i][j] - mnew);
                s[i][j] = p;
                rsum += p;
            }
#pragma unroll
            for (int o = 1; o < 8; o <<= 1)
                rsum += __shfl_xor_sync(0xffffffffu, rsum, o);
            l_i[i] = l_i[i] * alpha + rsum;
            m_i[i] = mnew;
#pragma unroll
            for (int j = 0; j < 8; j++) oacc[i][j] *= alpha;
        }

        __syncthreads();   // all Kts reads done before overwriting as Ps
#pragma unroll
        for (int i = 0; i < 4; i++) {
            *(float4*)&Ps[(ty * 4 + i) * 68 + tx * 8] =
                make_float4(s[i][0], s[i][1], s[i][2], s[i][3]);
            *(float4*)&Ps[(ty * 4 + i) * 68 + tx * 8 + 4] =
                make_float4(s[i][4], s[i][5], s[i][6], s[i][7]);
        }
        __syncthreads();

        // O += P @ V, chunked by 4 along s0; all smem reads are LDS.128.
#pragma unroll 2
        for (int s0 = 0; s0 < 64; s0 += 4) {
            float4 pf4[4];
#pragma unroll
            for (int i = 0; i < 4; i++)
                pf4[i] = *(const float4*)&Ps[(ty * 4 + i) * 68 + s0];
            float4 va[4], vb[4];
#pragma unroll
            for (int u = 0; u < 4; u++) {
                va[u] = *(const float4*)(Vs + (s0 + u) * 64 + tx * 8);
                vb[u] = *(const float4*)(Vs + (s0 + u) * 64 + tx * 8 + 4);
            }
#pragma unroll
            for (int u = 0; u < 4; u++) {
                float vf[8];
                *(float4*)&vf[0] = va[u];
                *(float4*)&vf[4] = vb[u];
#pragma unroll
                for (int i = 0; i < 4; i++) {
                    float p = ((const float*)&pf4[i])[u];
#pragma unroll
                    for (int j = 0; j < 8; j++)
                        oacc[i][j] += p * vf[j];
                }
            }
        }
    }

    // Normalize and write y[m][h*D + d] with vector stores.
#pragma unroll
    for (int i = 0; i < 4; i++) {
        float inv = 1.f / l_i[i];
        int t = qi * 64 + ty * 4 + i;
        float* dst = gy + ((long long)b * TT + t) * CC + h * DD + tx * 8;
        float4 o0 = make_float4(oacc[i][0] * inv, oacc[i][1] * inv,
                                oacc[i][2] * inv, oacc[i][3] * inv);
        float4 o1 = make_float4(oacc[i][4] * inv, oacc[i][5] * inv,
                                oacc[i][6] * inv, oacc[i][7] * inv);
        *(float4*)dst       = o0;
        *(float4*)(dst + 4) = o1;
    }
}

// ---------------------------------------------------------------------------
extern "C" void kernel_launch(void* const* d_in, const int* in_sizes, int n_in,
                              void* d_out, int out_size)
{
    const float* x  = (const float*)d_in[0];
    const float* Wq = (const float*)d_in[1];
    const float* bq = (const float*)d_in[2];
    const float* Wk = (const float*)d_in[3];
    const float* bk = (const float*)d_in[4];
    const float* Wv = (const float*)d_in[5];
    const float* bv = (const float*)d_in[6];
    const float* Wp = (const float*)d_in[7];
    const float* bp = (const float*)d_in[8];
    float* out = (float*)d_out;

    float *q, *k, *v, *y;
    cudaGetSymbolAddress((void**)&q, g_q);
    cudaGetSymbolAddress((void**)&k, g_k);
    cudaGetSymbolAddress((void**)&v, g_v);
    cudaGetSymbolAddress((void**)&y, g_y);

    dim3 gblk(256);
    dim3 ggrid(CC / 128, MM / 128);             // (8, 64)
    const int bias_blocks = (int)((long long)MM * CC / 4 / 256);   // 8192

    gemm_tc<<<ggrid, gblk>>>(x, Wq, q, MM, CC, CC);
    bias_add4<<<bias_blocks, 256>>>(q, bq);
    gemm_tc<<<ggrid, gblk>>>(x, Wk, k, MM, CC, CC);
    bias_add4<<<bias_blocks, 256>>>(k, bk);
    gemm_tc<<<ggrid, gblk>>>(x, Wv, v, MM, CC, CC);
    bias_add4<<<bias_blocks, 256>>>(v, bv);

    const int att_smem = ATT_SMEM_FLOATS * (int)sizeof(float);   // 51200 B
    cudaFuncSetAttribute(attn64, cudaFuncAttributeMaxDynamicSharedMemorySize,
                         att_smem);
    attn64<<<dim3(TT / 64, BB * HH), 128, att_smem>>>(q, k, v, y);

    gemm_tc<<<ggrid, gblk>>>(y, Wp, out, MM, CC, CC);
    bias_add4<<<bias_blocks, 256>>>(out, bp);
}